// round 12
// baseline (speedup 1.0000x reference)
#include <cuda_runtime.h>
#include <math.h>
#include <float.h>
#include <stdint.h>

// ---------------------------------------------------------------- constants
#define BATCH 2
#define SEQ   512
#define HID   1024
#define NHEAD 16
#define HDIM  64
#define NLAYER 4
#define FFD   4096
#define NCLS  14
#define TOK   (BATCH*SEQ)     // 1024
#define RSPAN 512             // 2*SPAN
#define ZBATCH (BATCH*NHEAD)  // 32

#define BM 128
#define BN 64
#define LDS_ 36               // BK(32) + 4 pad
#define SMEM_BYTES ((2*BM*LDS_ + 2*BN*LDS_) * 4)   // 55296

// ---------------------------------------------------------------- scratch
__device__ float g_x[TOK*HID];
__device__ float g_q[TOK*HID];          // transform-head output
__device__ float g_ctx[TOK*HID];
__device__ float g_tmp[TOK*HID];
__device__ float g_relln[RSPAN*HID];
__device__ float g_qkv[(size_t)TOK*3*HID];
__device__ float g_pos[(size_t)RSPAN*2*HID];      // [r][posq|posk]
__device__ float g_scores[(size_t)ZBATCH*SEQ*SEQ];
__device__ float g_c2p[(size_t)ZBATCH*SEQ*RSPAN];
__device__ float g_p2c[(size_t)ZBATCH*SEQ*RSPAN];
__device__ float g_p2cg[(size_t)ZBATCH*SEQ*SEQ];  // gathered, [z][q][k]
__device__ float g_ff[(size_t)TOK*FFD];
__device__ float g_maskf[TOK];
__device__ float g_nll[TOK];

__device__ __forceinline__ float gelu_exact(float x) {
    return 0.5f * x * (1.0f + erff(x * 0.70710678118654752440f));
}
__device__ __forceinline__ float tf32r(float x) {
    uint32_t u; asm("cvt.rna.tf32.f32 %0, %1;" : "=r"(u) : "f"(x));
    return __uint_as_float(u);
}
__device__ __forceinline__ void ldsm4(uint32_t* r, uint32_t addr) {
    asm volatile("ldmatrix.sync.aligned.m8n8.x4.shared.b16 {%0,%1,%2,%3}, [%4];"
                 : "=r"(r[0]), "=r"(r[1]), "=r"(r[2]), "=r"(r[3]) : "r"(addr));
}
__device__ __forceinline__ void mma_tf32(float* c, const uint32_t* a, uint32_t b0, uint32_t b1) {
    asm volatile(
        "mma.sync.aligned.m16n8k8.row.col.f32.tf32.tf32.f32 "
        "{%0,%1,%2,%3}, {%4,%5,%6,%7}, {%8,%9}, {%0,%1,%2,%3};"
        : "+f"(c[0]), "+f"(c[1]), "+f"(c[2]), "+f"(c[3])
        : "r"(a[0]), "r"(a[1]), "r"(a[2]), "r"(a[3]), "r"(b0), "r"(b1));
}

// DeBERTa log bucket: bucket value for rel offset d
__device__ __forceinline__ int bucketf(int rel) {
    int apos = (rel < 128 && rel > -128) ? 127 : (rel < 0 ? -rel : rel);
    if (apos <= 128) return rel;
    const float LOGC = logf(511.0f / 128.0f);
    float lp = ceilf(logf((float)apos / 128.0f) / LOGC * 127.0f) + 128.0f;
    return (int)(lp * (rel > 0 ? 1.0f : -1.0f));
}
// c2p index for (q,k):  clip(bucket(q-k)+256)
__device__ __forceinline__ int c2pi(int d) {
    int v = bucketf(d) + 256;
    return v < 0 ? 0 : (v > 511 ? 511 : v);
}
// p2c index for (k,q):  clip(-bucket(k-q)+256)   (monotone nonincreasing in d=k-q, step<=1)
__device__ __forceinline__ int p2ci(int d) {
    int v = -bucketf(d) + 256;
    return v < 0 ? 0 : (v > 511 ? 511 : v);
}

// ---------------------------------------------------------------- embed + LN + mask
__global__ void embed_kernel(const float* __restrict__ we, const float* __restrict__ sc,
                             const float* __restrict__ bi, const int* __restrict__ ids,
                             const int* __restrict__ att) {
    __shared__ float sm[HID];
    __shared__ float red[256];
    int t = blockIdx.x, tid = threadIdx.x;
    const float* row = we + (size_t)ids[t] * HID;
    float s1 = 0.f;
    for (int i = tid; i < HID; i += 256) { float v = row[i]; sm[i] = v; s1 += v; }
    red[tid] = s1; __syncthreads();
    for (int s = 128; s; s >>= 1) { if (tid < s) red[tid] += red[tid + s]; __syncthreads(); }
    float mu = red[0] * (1.0f / HID); __syncthreads();
    float s2 = 0.f;
    for (int i = tid; i < HID; i += 256) { float d = sm[i] - mu; s2 += d * d; }
    red[tid] = s2; __syncthreads();
    for (int s = 128; s; s >>= 1) { if (tid < s) red[tid] += red[tid + s]; __syncthreads(); }
    float inv = rsqrtf(red[0] * (1.0f / HID) + 1e-7f);
    float mf = (float)att[t];
    if (tid == 0) g_maskf[t] = mf;
    for (int i = tid; i < HID; i += 256)
        g_x[(size_t)t * HID + i] = ((sm[i] - mu) * inv * sc[i] + bi[i]) * mf;
}

// ---------------------------------------------------------------- plain row LN
__global__ void ln_kernel(const float* __restrict__ in, const float* __restrict__ sc,
                          const float* __restrict__ bi, float* __restrict__ out) {
    __shared__ float sm[HID];
    __shared__ float red[256];
    int t = blockIdx.x, tid = threadIdx.x;
    const float* row = in + (size_t)t * HID;
    float s1 = 0.f;
    for (int i = tid; i < HID; i += 256) { float v = row[i]; sm[i] = v; s1 += v; }
    red[tid] = s1; __syncthreads();
    for (int s = 128; s; s >>= 1) { if (tid < s) red[tid] += red[tid + s]; __syncthreads(); }
    float mu = red[0] * (1.0f / HID); __syncthreads();
    float s2 = 0.f;
    for (int i = tid; i < HID; i += 256) { float d = sm[i] - mu; s2 += d * d; }
    red[tid] = s2; __syncthreads();
    for (int s = 128; s; s >>= 1) { if (tid < s) red[tid] += red[tid + s]; __syncthreads(); }
    float inv = rsqrtf(red[0] * (1.0f / HID) + 1e-7f);
    for (int i = tid; i < HID; i += 256)
        out[(size_t)t * HID + i] = (sm[i] - mu) * inv * sc[i] + bi[i];
}

// ---------------------------------------------------------------- residual + LN
__global__ void add_ln_kernel(const float* __restrict__ x, const float* __restrict__ d,
                              const float* __restrict__ sc, const float* __restrict__ bi,
                              float* __restrict__ out) {
    __shared__ float sm[HID];
    __shared__ float red[256];
    int t = blockIdx.x, tid = threadIdx.x;
    float s1 = 0.f;
    for (int i = tid; i < HID; i += 256) {
        float v = x[(size_t)t * HID + i] + d[(size_t)t * HID + i];
        sm[i] = v; s1 += v;
    }
    red[tid] = s1; __syncthreads();
    for (int s = 128; s; s >>= 1) { if (tid < s) red[tid] += red[tid + s]; __syncthreads(); }
    float mu = red[0] * (1.0f / HID); __syncthreads();
    float s2 = 0.f;
    for (int i = tid; i < HID; i += 256) { float dv = sm[i] - mu; s2 += dv * dv; }
    red[tid] = s2; __syncthreads();
    for (int s = 128; s; s >>= 1) { if (tid < s) red[tid] += red[tid + s]; __syncthreads(); }
    float inv = rsqrtf(red[0] * (1.0f / HID) + 1e-7f);
    for (int i = tid; i < HID; i += 256)
        out[(size_t)t * HID + i] = (sm[i] - mu) * inv * sc[i] + bi[i];
}

// ---------------------------------------------------------------- TF32 tensor-core GEMM
// C[M,N] = A[M,K] @ B (+bias) (+gelu).  128x64 tile, BK=32, 256 thr.
// NNB=0: B is [N][K] (NT).  NNB=1: B is [K][N] row-major (NN, weights/V direct).
// Batched via z = blockIdx.z: bb = z>>4, hh = z&15.
template<int NNB, int HAS_BIAS, int ACT>
__global__ void __launch_bounds__(256, 2) gemm_tc(
    const float* __restrict__ A, const float* __restrict__ B,
    const float* __restrict__ bias, float* __restrict__ C,
    int K, int lda, int ldb, int ldc,
    long aB, long aH, long bB, long bH, long cB, long cH)
{
    extern __shared__ float smem[];
    float* As = smem;                      // [2][BM*LDS_]
    float* Bs = smem + 2 * BM * LDS_;      // [2][BN*LDS_]
    const int tid = threadIdx.x;
    const int lane = tid & 31, wid = tid >> 5;
    const int wm = (wid & 3) * 32, wn = (wid >> 2) * 32;
    const int z = blockIdx.z, bb = z >> 4, hh = z & 15;
    const float* Az = A + (size_t)bb * aB + (size_t)hh * aH;
    const float* Bz = B + (size_t)bb * bB + (size_t)hh * bH;
    float*       Cz = C + (size_t)bb * cB + (size_t)hh * cH;
    const int bm = blockIdx.y * BM, bn = blockIdx.x * BN;

    const uint32_t sA = (uint32_t)__cvta_generic_to_shared(As);
    const uint32_t sB = (uint32_t)__cvta_generic_to_shared(Bs);

    // ldmatrix lane geometry (b16-pair trick for tf32)
    const int a_row = (lane & 7) + ((lane >> 3) & 1) * 8;
    const int a_kad = (lane >> 4) * 4;
    const int b_row = (lane & 7) + (lane >> 4) * 8;
    const int b_kad = ((lane >> 3) & 1) * 4;

    // NN B lane map: spread 4 k-rows across each warp so transposed sts hits 8 banks
    const int nn_k = wid * 4 + (lane >> 3);        // 0..31
    const int nn_n = (lane & 7) * 4;               // 0..28

    float4 aR[4], bR[2];
    auto ldg = [&](int k0) {
#pragma unroll
        for (int i = 0; i < 4; i++) {
            int id = tid + i * 256;
            aR[i] = *(const float4*)(Az + (size_t)(bm + (id >> 3)) * lda + k0 + (id & 7) * 4);
        }
        if (NNB) {
#pragma unroll
            for (int c = 0; c < 2; c++)
                bR[c] = *(const float4*)(Bz + (size_t)(k0 + nn_k) * ldb + bn + nn_n + 32 * c);
        } else {
#pragma unroll
            for (int i = 0; i < 2; i++) {
                int id = tid + i * 256;
                bR[i] = *(const float4*)(Bz + (size_t)(bn + (id >> 3)) * ldb + k0 + (id & 7) * 4);
            }
        }
    };
    auto sts = [&](int buf) {
        float* Ab = As + buf * BM * LDS_;
        float* Bb = Bs + buf * BN * LDS_;
#pragma unroll
        for (int i = 0; i < 4; i++) {
            int id = tid + i * 256;
            float4 v = aR[i];
            float4 w = make_float4(tf32r(v.x), tf32r(v.y), tf32r(v.z), tf32r(v.w));
            *(float4*)(Ab + (id >> 3) * LDS_ + (id & 7) * 4) = w;
        }
        if (NNB) {
#pragma unroll
            for (int c = 0; c < 2; c++) {
                float4 v = bR[c];
                int n = nn_n + 32 * c;
                Bb[(n + 0) * LDS_ + nn_k] = tf32r(v.x);
                Bb[(n + 1) * LDS_ + nn_k] = tf32r(v.y);
                Bb[(n + 2) * LDS_ + nn_k] = tf32r(v.z);
                Bb[(n + 3) * LDS_ + nn_k] = tf32r(v.w);
            }
        } else {
#pragma unroll
            for (int i = 0; i < 2; i++) {
                int id = tid + i * 256;
                float4 v = bR[i];
                float4 w = make_float4(tf32r(v.x), tf32r(v.y), tf32r(v.z), tf32r(v.w));
                *(float4*)(Bb + (id >> 3) * LDS_ + (id & 7) * 4) = w;
            }
        }
    };

    float acc[2][4][4];
#pragma unroll
    for (int i = 0; i < 2; i++)
#pragma unroll
        for (int j = 0; j < 4; j++)
#pragma unroll
            for (int c = 0; c < 4; c++) acc[i][j][c] = 0.f;

    ldg(0);
    sts(0);
    __syncthreads();
    const int nk = K >> 5;
    for (int kt = 0; kt < nk; kt++) {
        int cur = kt & 1;
        if (kt + 1 < nk) ldg((kt + 1) * 32);
        uint32_t baseA = sA + (uint32_t)(cur * BM * LDS_) * 4u;
        uint32_t baseB = sB + (uint32_t)(cur * BN * LDS_) * 4u;
#pragma unroll
        for (int kk = 0; kk < 32; kk += 8) {
            uint32_t a[2][4], b[2][4];
#pragma unroll
            for (int i = 0; i < 2; i++)
                ldsm4(a[i], baseA + (uint32_t)((wm + 16 * i + a_row) * LDS_ + kk + a_kad) * 4u);
#pragma unroll
            for (int j2 = 0; j2 < 2; j2++)
                ldsm4(b[j2], baseB + (uint32_t)((wn + 16 * j2 + b_row) * LDS_ + kk + b_kad) * 4u);
#pragma unroll
            for (int i = 0; i < 2; i++)
#pragma unroll
                for (int j = 0; j < 4; j++)
                    mma_tf32(acc[i][j], a[i], b[j >> 1][(j & 1) * 2], b[j >> 1][(j & 1) * 2 + 1]);
        }
        if (kt + 1 < nk) {
            __syncthreads();
            sts(cur ^ 1);
            __syncthreads();
        }
    }

    const int r = lane >> 2, cp = (lane & 3) * 2;
#pragma unroll
    for (int i = 0; i < 2; i++) {
#pragma unroll
        for (int j = 0; j < 4; j++) {
            int row0 = bm + wm + 16 * i + r;
            int col  = bn + wn + 8 * j + cp;
            float2 bb2 = make_float2(0.f, 0.f);
            if (HAS_BIAS) bb2 = *(const float2*)(bias + col);
            float2 v0 = make_float2(acc[i][j][0] + bb2.x, acc[i][j][1] + bb2.y);
            float2 v1 = make_float2(acc[i][j][2] + bb2.x, acc[i][j][3] + bb2.y);
            if (ACT) {
                v0.x = gelu_exact(v0.x); v0.y = gelu_exact(v0.y);
                v1.x = gelu_exact(v1.x); v1.y = gelu_exact(v1.y);
            }
            *(float2*)(Cz + (size_t)row0 * ldc + col) = v0;
            *(float2*)(Cz + (size_t)(row0 + 8) * ldc + col) = v1;
        }
    }
}

// ---------------------------------------------------------------- p2c gather staging
// p2cg[z][q][k] = p2c[z][k][p2ci(k-q)]   (coalesced both sides via 64x136 smem window)
// Window start is 16B-aligned; index span per 64x64 tile is <=126, +3 alignment slack
// => <=130 needed, 136 staged.
__global__ void p2c_gather_kernel() {
    __shared__ float sm[64][140];
    int z = blockIdx.z;
    int k0 = blockIdx.y * 64, q0 = blockIdx.x * 64;
    int tid = threadIdx.x;
    int w0 = p2ci(k0 + 63 - q0) & ~3;     // min index over tile, rounded DOWN to float4 alignment
    if (w0 > RSPAN - 136) w0 = RSPAN - 136;   // 376, still 4-aligned
    const float* src = g_p2c + (size_t)z * SEQ * RSPAN;
#pragma unroll
    for (int it = 0; it < 9; it++) {
        int idx = tid + it * 256;            // 64 rows x 34 float4
        if (idx < 64 * 34) {
            int row = idx / 34, c = idx - row * 34;
            *(float4*)&sm[row][c * 4] =
                *(const float4*)(src + (size_t)(k0 + row) * RSPAN + w0 + c * 4);
        }
    }
    __syncthreads();
    float* dst = g_p2cg + (size_t)z * SEQ * SEQ;
    int kl = tid & 63;
    int qb = tid >> 6;
#pragma unroll
    for (int it = 0; it < 16; it++) {
        int ql = qb + it * 4;
        int idx = p2ci((k0 + kl) - (q0 + ql));
        dst[(size_t)(q0 + ql) * SEQ + k0 + kl] = sm[kl][idx - w0];
    }
}

// ---------------------------------------------------------------- combine + scale + mask + XSoftmax
__global__ void softmax_kernel() {
    __shared__ float red[256];
    __shared__ float smc[RSPAN];
    int zq = blockIdx.x;
    int z = zq >> 9, q = zq & 511;
    int bb = z / NHEAD;
    int tid = threadIdx.x;
    const float SCALE = sqrtf(192.0f);  // sqrt(D*3)
    float mq = g_maskf[bb * SEQ + q];
    size_t rowS = ((size_t)z * SEQ + q) * SEQ;
    const float* c2pr = g_c2p + ((size_t)z * SEQ + q) * RSPAN;
    smc[tid] = c2pr[tid];
    smc[tid + 256] = c2pr[tid + 256];
    __syncthreads();

    int k0 = tid, k1 = tid + 256;
    float s0 = g_scores[rowS + k0] + smc[c2pi(q - k0)] + g_p2cg[rowS + k0];
    float s1 = g_scores[rowS + k1] + smc[c2pi(q - k1)] + g_p2cg[rowS + k1];
    s0 /= SCALE; s1 /= SCALE;
    bool m0 = (mq * g_maskf[bb * SEQ + k0]) > 0.f;
    bool m1 = (mq * g_maskf[bb * SEQ + k1]) > 0.f;
    float v0 = m0 ? s0 : -FLT_MAX;
    float v1 = m1 ? s1 : -FLT_MAX;

    red[tid] = fmaxf(v0, v1); __syncthreads();
    for (int s = 128; s; s >>= 1) { if (tid < s) red[tid] = fmaxf(red[tid], red[tid + s]); __syncthreads(); }
    float mx = red[0]; __syncthreads();

    float p0 = m0 ? expf(v0 - mx) : 0.f;
    float p1 = m1 ? expf(v1 - mx) : 0.f;
    red[tid] = p0 + p1; __syncthreads();
    for (int s = 128; s; s >>= 1) { if (tid < s) red[tid] += red[tid + s]; __syncthreads(); }
    float sum = red[0];
    float inv = (sum > 0.f) ? (1.0f / sum) : 0.f;
    g_scores[rowS + k0] = p0 * inv;
    g_scores[rowS + k1] = p1 * inv;
}

// ---------------------------------------------------------------- decoder + per-token NLL
__global__ void decoder_kernel(const float* __restrict__ tin, const float* __restrict__ Wd,
                               const float* __restrict__ bd, const int* __restrict__ labels,
                               float* __restrict__ out, int out_size) {
    __shared__ float sm[HID];
    __shared__ float red[256];
    __shared__ float lg[NCLS];
    int t = blockIdx.x, tid = threadIdx.x;
    for (int i = tid; i < HID; i += 256) sm[i] = tin[(size_t)t * HID + i];
    __syncthreads();
    for (int c = 0; c < NCLS; c++) {
        float p = 0.f;
        for (int k = tid; k < HID; k += 256) p += sm[k] * Wd[(size_t)k * NCLS + c];
        red[tid] = p; __syncthreads();
        for (int s = 128; s; s >>= 1) { if (tid < s) red[tid] += red[tid + s]; __syncthreads(); }
        if (tid == 0) lg[c] = red[0] + bd[c];
        __syncthreads();
    }
    if (out_size >= TOK * NCLS && tid < NCLS) out[(size_t)t * NCLS + tid] = lg[tid];
    if (tid == 0) {
        float mx = -FLT_MAX;
        for (int c = 0; c < NCLS; c++) mx = fmaxf(mx, lg[c]);
        float se = 0.f;
        for (int c = 0; c < NCLS; c++) se += expf(lg[c] - mx);
        float lse = mx + logf(se);
        g_nll[t] = (lse - lg[labels[t]]) * g_maskf[t];
    }
}

// ---------------------------------------------------------------- final deterministic loss reduce
__global__ void loss_kernel(float* __restrict__ out, int out_size) {
    __shared__ float rn[256], rd[256];
    int tid = threadIdx.x;
    float a = 0.f, d = 0.f;
    for (int t = tid; t < TOK; t += 256) { a += g_nll[t]; d += g_maskf[t]; }
    rn[tid] = a; rd[tid] = d; __syncthreads();
    for (int s = 128; s; s >>= 1) {
        if (tid < s) { rn[tid] += rn[tid + s]; rd[tid] += rd[tid + s]; }
        __syncthreads();
    }
    if (tid == 0) {
        float loss = rn[0] / fmaxf(rd[0], 1.0f);
        if (out_size > TOK * NCLS) out[TOK * NCLS] = loss;
        else if (out_size == 1)    out[0] = loss;
    }
}

// ---------------------------------------------------------------- launch
extern "C" void kernel_launch(void* const* d_in, const int* in_sizes, int n_in,
                              void* d_out, int out_size) {
    const float* word_emb = (const float*)d_in[0];
    const float* emb_ln_s = (const float*)d_in[1];
    const float* emb_ln_b = (const float*)d_in[2];
    const float* rel_emb  = (const float*)d_in[3];
    const float* rel_ln_s = (const float*)d_in[4];
    const float* rel_ln_b = (const float*)d_in[5];
    const float* Wq = (const float*)d_in[6];   const float* bq = (const float*)d_in[7];
    const float* Wk = (const float*)d_in[8];   const float* bk = (const float*)d_in[9];
    const float* Wv = (const float*)d_in[10];  const float* bv = (const float*)d_in[11];
    const float* Wo = (const float*)d_in[12];  const float* bo = (const float*)d_in[13];
    const float* ln1_s = (const float*)d_in[14]; const float* ln1_b = (const float*)d_in[15];
    const float* W1 = (const float*)d_in[16];  const float* b1 = (const float*)d_in[17];
    const float* W2 = (const float*)d_in[18];  const float* b2 = (const float*)d_in[19];
    const float* ln2_s = (const float*)d_in[20]; const float* ln2_b = (const float*)d_in[21];
    const float* Wt = (const float*)d_in[22];  const float* bt = (const float*)d_in[23];
    const float* tln_s = (const float*)d_in[24]; const float* tln_b = (const float*)d_in[25];
    const float* Wd = (const float*)d_in[26];  const float* bd = (const float*)d_in[27];
    const int* ids    = (const int*)d_in[28];
    const int* att    = (const int*)d_in[29];
    const int* labels = (const int*)d_in[30];
    float* out = (float*)d_out;
    (void)in_sizes; (void)n_in;

    cudaFuncSetAttribute(gemm_tc<0,0,0>, cudaFuncAttributeMaxDynamicSharedMemorySize, SMEM_BYTES);
    cudaFuncSetAttribute(gemm_tc<1,0,0>, cudaFuncAttributeMaxDynamicSharedMemorySize, SMEM_BYTES);
    cudaFuncSetAttribute(gemm_tc<1,1,0>, cudaFuncAttributeMaxDynamicSharedMemorySize, SMEM_BYTES);
    cudaFuncSetAttribute(gemm_tc<1,1,1>, cudaFuncAttributeMaxDynamicSharedMemorySize, SMEM_BYTES);

    float *x, *qbuf, *ctx, *tmp, *relln, *qkv, *pos, *scores, *c2p, *p2c, *ff;
    cudaGetSymbolAddress((void**)&x, g_x);       cudaGetSymbolAddress((void**)&qbuf, g_q);
    cudaGetSymbolAddress((void**)&ctx, g_ctx);   cudaGetSymbolAddress((void**)&tmp, g_tmp);
    cudaGetSymbolAddress((void**)&relln, g_relln);
    cudaGetSymbolAddress((void**)&qkv, g_qkv);   cudaGetSymbolAddress((void**)&pos, g_pos);
    cudaGetSymbolAddress((void**)&scores, g_scores);
    cudaGetSymbolAddress((void**)&c2p, g_c2p);   cudaGetSymbolAddress((void**)&p2c, g_p2c);
    cudaGetSymbolAddress((void**)&ff, g_ff);

    embed_kernel<<<TOK, 256>>>(word_emb, emb_ln_s, emb_ln_b, ids, att);
    ln_kernel<<<RSPAN, 256>>>(rel_emb, rel_ln_s, rel_ln_b, relln);

    const long SH3 = (long)SEQ * 3 * HID;
    const long SS  = (long)SEQ * SEQ;
    const long SR  = (long)SEQ * RSPAN;
    const size_t HH = (size_t)HID * HID;

    for (int l = 0; l < NLAYER; l++) {
        const float* wq = Wq + l * HH;  const float* bql = bq + (size_t)l * HID;
        const float* wk = Wk + l * HH;  const float* bkl = bk + (size_t)l * HID;
        const float* wv = Wv + l * HH;  const float* bvl = bv + (size_t)l * HID;
        const float* wo = Wo + l * HH;  const float* bol = bo + (size_t)l * HID;
        const float* w1 = W1 + (size_t)l * HID * FFD;  const float* b1l = b1 + (size_t)l * FFD;
        const float* w2 = W2 + (size_t)l * FFD * HID;  const float* b2l = b2 + (size_t)l * HID;

        // QKV projections (NN, weights direct), interleaved into qkv [t][3*HID]
        gemm_tc<1,1,0><<<dim3(HID/BN, TOK/BM), 256, SMEM_BYTES>>>(
            x, wq, bql, qkv,          HID, HID, HID, 3*HID, 0,0,0,0,0,0);
        gemm_tc<1,1,0><<<dim3(HID/BN, TOK/BM), 256, SMEM_BYTES>>>(
            x, wk, bkl, qkv + HID,    HID, HID, HID, 3*HID, 0,0,0,0,0,0);
        gemm_tc<1,1,0><<<dim3(HID/BN, TOK/BM), 256, SMEM_BYTES>>>(
            x, wv, bvl, qkv + 2*HID,  HID, HID, HID, 3*HID, 0,0,0,0,0,0);
        // positional projections: pos = [posq | posk], [512][2048]
        gemm_tc<1,1,0><<<dim3(HID/BN, RSPAN/BM), 256, SMEM_BYTES>>>(
            relln, wq, bql, pos,       HID, HID, HID, 2*HID, 0,0,0,0,0,0);
        gemm_tc<1,1,0><<<dim3(HID/BN, RSPAN/BM), 256, SMEM_BYTES>>>(
            relln, wk, bkl, pos + HID, HID, HID, HID, 2*HID, 0,0,0,0,0,0);

        // scores[b,h,q,k] = q.k   (NT)
        gemm_tc<0,0,0><<<dim3(SEQ/BN, SEQ/BM, ZBATCH), 256, SMEM_BYTES>>>(
            qkv, qkv + HID, nullptr, scores, HDIM, 3*HID, 3*HID, SEQ,
            SH3, (long)HDIM, SH3, (long)HDIM, (long)NHEAD * SS, SS);
        // c2p[b,h,q,r] = q.posk[r]   (NT)
        gemm_tc<0,0,0><<<dim3(RSPAN/BN, SEQ/BM, ZBATCH), 256, SMEM_BYTES>>>(
            qkv, pos + HID, nullptr, c2p, HDIM, 3*HID, 2*HID, RSPAN,
            SH3, (long)HDIM, 0L, (long)HDIM, (long)NHEAD * SR, SR);
        // p2c[b,h,k,r] = k.posq[r]   (NT)
        gemm_tc<0,0,0><<<dim3(RSPAN/BN, SEQ/BM, ZBATCH), 256, SMEM_BYTES>>>(
            qkv + HID, pos, nullptr, p2c, HDIM, 3*HID, 2*HID, RSPAN,
            SH3, (long)HDIM, 0L, (long)HDIM, (long)NHEAD * SR, SR);

        p2c_gather_kernel<<<dim3(SEQ/64, SEQ/64, ZBATCH), 256>>>();
        softmax_kernel<<<ZBATCH * SEQ, 256>>>();

        // ctx = probs @ V   (NN, V read in-place from qkv)
        gemm_tc<1,0,0><<<dim3(HDIM/BN, SEQ/BM, ZBATCH), 256, SMEM_BYTES>>>(
            scores, qkv + 2*HID, nullptr, ctx, SEQ, SEQ, 3*HID, HID,
            (long)NHEAD * SS, SS, SH3, (long)HDIM, (long)SEQ * HID, (long)HDIM);

        gemm_tc<1,1,0><<<dim3(HID/BN, TOK/BM), 256, SMEM_BYTES>>>(
            ctx, wo, bol, tmp, HID, HID, HID, HID, 0,0,0,0,0,0);
        add_ln_kernel<<<TOK, 256>>>(x, tmp, ln1_s + (size_t)l*HID, ln1_b + (size_t)l*HID, x);

        gemm_tc<1,1,1><<<dim3(FFD/BN, TOK/BM), 256, SMEM_BYTES>>>(
            x, w1, b1l, ff, HID, HID, FFD, FFD, 0,0,0,0,0,0);
        gemm_tc<1,1,0><<<dim3(HID/BN, TOK/BM), 256, SMEM_BYTES>>>(
            ff, w2, b2l, tmp, FFD, FFD, HID, HID, 0,0,0,0,0,0);
        add_ln_kernel<<<TOK, 256>>>(x, tmp, ln2_s + (size_t)l*HID, ln2_b + (size_t)l*HID, x);
    }

    // transform head: LN(gelu(x @ Wt + bt))
    gemm_tc<1,1,1><<<dim3(HID/BN, TOK/BM), 256, SMEM_BYTES>>>(
        x, Wt, bt, tmp, HID, HID, HID, HID, 0,0,0,0,0,0);
    ln_kernel<<<TOK, 256>>>(tmp, tln_s, tln_b, qbuf);

    decoder_kernel<<<TOK, 256>>>(qbuf, Wd, bd, labels, out, out_size);
    loss_kernel<<<1, 256>>>(out, out_size);
}

// round 13
// speedup vs baseline: 1.0765x; 1.0765x over previous
#include <cuda_runtime.h>
#include <math.h>
#include <float.h>
#include <stdint.h>

// ---------------------------------------------------------------- constants
#define BATCH 2
#define SEQ   512
#define HID   1024
#define NHEAD 16
#define HDIM  64
#define NLAYER 4
#define FFD   4096
#define NCLS  14
#define TOK   (BATCH*SEQ)     // 1024
#define RSPAN 512             // 2*SPAN
#define ZBATCH (BATCH*NHEAD)  // 32

#define BN 64
#define LDS_ 36               // BK(32) + 4 pad
#define SMEM4 ((2*128*LDS_ + 2*64*LDS_) * 4)   // 55296 (BM=128)
#define SMEM2 ((2*64*LDS_  + 2*64*LDS_) * 4)   // 36864 (BM=64)

// ---------------------------------------------------------------- scratch
__device__ float g_x[TOK*HID];
__device__ float g_q[TOK*HID];          // transform-head output
__device__ float g_ctx[TOK*HID];
__device__ float g_tmp[TOK*HID];
__device__ float g_relln[RSPAN*HID];
__device__ float g_qkv[(size_t)TOK*3*HID];
__device__ float g_pos[(size_t)RSPAN*2*HID];      // [r][posq|posk]
__device__ float g_scores[(size_t)ZBATCH*SEQ*SEQ];
__device__ float g_c2p[(size_t)ZBATCH*SEQ*RSPAN];
__device__ float g_p2c[(size_t)ZBATCH*SEQ*RSPAN];
__device__ float g_p2cg[(size_t)ZBATCH*SEQ*SEQ];  // gathered, [z][q][k]
__device__ float g_ff[(size_t)TOK*FFD];
__device__ float g_maskf[TOK];
__device__ float g_nll[TOK];

__device__ __forceinline__ float gelu_exact(float x) {
    return 0.5f * x * (1.0f + erff(x * 0.70710678118654752440f));
}
__device__ __forceinline__ float tf32r(float x) {
    uint32_t u; asm("cvt.rna.tf32.f32 %0, %1;" : "=r"(u) : "f"(x));
    return __uint_as_float(u);
}
__device__ __forceinline__ void ldsm4(uint32_t* r, uint32_t addr) {
    asm volatile("ldmatrix.sync.aligned.m8n8.x4.shared.b16 {%0,%1,%2,%3}, [%4];"
                 : "=r"(r[0]), "=r"(r[1]), "=r"(r[2]), "=r"(r[3]) : "r"(addr));
}
__device__ __forceinline__ void mma_tf32(float* c, const uint32_t* a, uint32_t b0, uint32_t b1) {
    asm volatile(
        "mma.sync.aligned.m16n8k8.row.col.f32.tf32.tf32.f32 "
        "{%0,%1,%2,%3}, {%4,%5,%6,%7}, {%8,%9}, {%0,%1,%2,%3};"
        : "+f"(c[0]), "+f"(c[1]), "+f"(c[2]), "+f"(c[3])
        : "r"(a[0]), "r"(a[1]), "r"(a[2]), "r"(a[3]), "r"(b0), "r"(b1));
}

// DeBERTa log bucket
__device__ __forceinline__ int bucketf(int rel) {
    int apos = (rel < 128 && rel > -128) ? 127 : (rel < 0 ? -rel : rel);
    if (apos <= 128) return rel;
    const float LOGC = logf(511.0f / 128.0f);
    float lp = ceilf(logf((float)apos / 128.0f) / LOGC * 127.0f) + 128.0f;
    return (int)(lp * (rel > 0 ? 1.0f : -1.0f));
}
__device__ __forceinline__ int c2pi(int d) {
    int v = bucketf(d) + 256;
    return v < 0 ? 0 : (v > 511 ? 511 : v);
}
__device__ __forceinline__ int p2ci(int d) {
    int v = -bucketf(d) + 256;
    return v < 0 ? 0 : (v > 511 ? 511 : v);
}

// ---------------------------------------------------------------- embed + LN + mask
__global__ void embed_kernel(const float* __restrict__ we, const float* __restrict__ sc,
                             const float* __restrict__ bi, const int* __restrict__ ids,
                             const int* __restrict__ att) {
    __shared__ float sm[HID];
    __shared__ float red[256];
    int t = blockIdx.x, tid = threadIdx.x;
    const float* row = we + (size_t)ids[t] * HID;
    float s1 = 0.f;
    for (int i = tid; i < HID; i += 256) { float v = row[i]; sm[i] = v; s1 += v; }
    red[tid] = s1; __syncthreads();
    for (int s = 128; s; s >>= 1) { if (tid < s) red[tid] += red[tid + s]; __syncthreads(); }
    float mu = red[0] * (1.0f / HID); __syncthreads();
    float s2 = 0.f;
    for (int i = tid; i < HID; i += 256) { float d = sm[i] - mu; s2 += d * d; }
    red[tid] = s2; __syncthreads();
    for (int s = 128; s; s >>= 1) { if (tid < s) red[tid] += red[tid + s]; __syncthreads(); }
    float inv = rsqrtf(red[0] * (1.0f / HID) + 1e-7f);
    float mf = (float)att[t];
    if (tid == 0) g_maskf[t] = mf;
    for (int i = tid; i < HID; i += 256)
        g_x[(size_t)t * HID + i] = ((sm[i] - mu) * inv * sc[i] + bi[i]) * mf;
}

// ---------------------------------------------------------------- plain row LN
__global__ void ln_kernel(const float* __restrict__ in, const float* __restrict__ sc,
                          const float* __restrict__ bi, float* __restrict__ out) {
    __shared__ float sm[HID];
    __shared__ float red[256];
    int t = blockIdx.x, tid = threadIdx.x;
    const float* row = in + (size_t)t * HID;
    float s1 = 0.f;
    for (int i = tid; i < HID; i += 256) { float v = row[i]; sm[i] = v; s1 += v; }
    red[tid] = s1; __syncthreads();
    for (int s = 128; s; s >>= 1) { if (tid < s) red[tid] += red[tid + s]; __syncthreads(); }
    float mu = red[0] * (1.0f / HID); __syncthreads();
    float s2 = 0.f;
    for (int i = tid; i < HID; i += 256) { float d = sm[i] - mu; s2 += d * d; }
    red[tid] = s2; __syncthreads();
    for (int s = 128; s; s >>= 1) { if (tid < s) red[tid] += red[tid + s]; __syncthreads(); }
    float inv = rsqrtf(red[0] * (1.0f / HID) + 1e-7f);
    for (int i = tid; i < HID; i += 256)
        out[(size_t)t * HID + i] = (sm[i] - mu) * inv * sc[i] + bi[i];
}

// ---------------------------------------------------------------- residual + LN
__global__ void add_ln_kernel(const float* __restrict__ x, const float* __restrict__ d,
                              const float* __restrict__ sc, const float* __restrict__ bi,
                              float* __restrict__ out) {
    __shared__ float sm[HID];
    __shared__ float red[256];
    int t = blockIdx.x, tid = threadIdx.x;
    float s1 = 0.f;
    for (int i = tid; i < HID; i += 256) {
        float v = x[(size_t)t * HID + i] + d[(size_t)t * HID + i];
        sm[i] = v; s1 += v;
    }
    red[tid] = s1; __syncthreads();
    for (int s = 128; s; s >>= 1) { if (tid < s) red[tid] += red[tid + s]; __syncthreads(); }
    float mu = red[0] * (1.0f / HID); __syncthreads();
    float s2 = 0.f;
    for (int i = tid; i < HID; i += 256) { float dv = sm[i] - mu; s2 += dv * dv; }
    red[tid] = s2; __syncthreads();
    for (int s = 128; s; s >>= 1) { if (tid < s) red[tid] += red[tid + s]; __syncthreads(); }
    float inv = rsqrtf(red[0] * (1.0f / HID) + 1e-7f);
    for (int i = tid; i < HID; i += 256)
        out[(size_t)t * HID + i] = (sm[i] - mu) * inv * sc[i] + bi[i];
}

// ---------------------------------------------------------------- TF32 tensor-core GEMM (multi-set)
// Up to 3 independent GEMM "sets" per launch; set = blockIdx.z / nb, batch zz = z % nb,
// per-batch: bb = zz>>4, hh = zz&15. MW = warps along M (4 -> BM=128, 2 -> BM=64).
// NNB=0: B is [N][K] (NT).  NNB=1: B is [K][N] (NN).
struct GSet {
    const float* A; const float* B; const float* bias; float* C;
    long aB, aH, bB, bH, cB, cH;
    int lda, ldb, ldc;
};

template<int MW, int NNB, int HAS_BIAS, int ACT>
__global__ void __launch_bounds__(256, MW == 2 ? 3 : 2) gemm_tc(
    GSet s0, GSet s1, GSet s2, int nb, int K)
{
    constexpr int TBM = MW * 32;          // block M
    constexpr int NB16 = 32 / (256 / (MW * 32)) / 8;  // 2 for MW=4, 1 for MW=2
    constexpr int JT = NB16 * 2;          // mma n-tiles per warp
    extern __shared__ float smem[];
    float* As = smem;                      // [2][TBM*LDS_]
    float* Bs = smem + 2 * TBM * LDS_;     // [2][BN*LDS_]
    const int tid = threadIdx.x;
    const int lane = tid & 31, wid = tid >> 5;
    const int wm = (wid % MW) * 32, wn = (wid / MW) * (NB16 * 16);

    const int z = blockIdx.z;
    const int set = z / nb, zz = z - set * nb;
    const int bb = zz >> 4, hh = zz & 15;
    const float *Az, *Bz, *biasp; float* Cz; int lda, ldb, ldc;
    {
        const GSet& s = (set == 0) ? s0 : (set == 1) ? s1 : s2;
        Az = s.A + (size_t)bb * s.aB + (size_t)hh * s.aH;
        Bz = s.B + (size_t)bb * s.bB + (size_t)hh * s.bH;
        biasp = s.bias;
        Cz = s.C + (size_t)bb * s.cB + (size_t)hh * s.cH;
        lda = s.lda; ldb = s.ldb; ldc = s.ldc;
    }
    const int bm = blockIdx.y * TBM, bn = blockIdx.x * BN;

    const uint32_t sA = (uint32_t)__cvta_generic_to_shared(As);
    const uint32_t sB = (uint32_t)__cvta_generic_to_shared(Bs);

    // ldmatrix lane geometry (b16-pair trick for tf32)
    const int a_row = (lane & 7) + ((lane >> 3) & 1) * 8;
    const int a_kad = (lane >> 4) * 4;
    const int b_row = (lane & 7) + (lane >> 4) * 8;
    const int b_kad = ((lane >> 3) & 1) * 4;

    // NN B lane map: 4 k-rows per warp, transposed scalar sts
    const int nn_k = wid * 4 + (lane >> 3);        // 0..31
    const int nn_n = (lane & 7) * 4;               // 0..28

    float4 aR[MW], bR[2];
    auto ldg = [&](int k0) {
#pragma unroll
        for (int i = 0; i < MW; i++) {
            int id = tid + i * 256;
            aR[i] = *(const float4*)(Az + (size_t)(bm + (id >> 3)) * lda + k0 + (id & 7) * 4);
        }
        if (NNB) {
#pragma unroll
            for (int c = 0; c < 2; c++)
                bR[c] = *(const float4*)(Bz + (size_t)(k0 + nn_k) * ldb + bn + nn_n + 32 * c);
        } else {
#pragma unroll
            for (int i = 0; i < 2; i++) {
                int id = tid + i * 256;
                bR[i] = *(const float4*)(Bz + (size_t)(bn + (id >> 3)) * ldb + k0 + (id & 7) * 4);
            }
        }
    };
    auto sts = [&](int buf) {
        float* Ab = As + buf * TBM * LDS_;
        float* Bb = Bs + buf * BN * LDS_;
#pragma unroll
        for (int i = 0; i < MW; i++) {
            int id = tid + i * 256;
            float4 v = aR[i];
            float4 w = make_float4(tf32r(v.x), tf32r(v.y), tf32r(v.z), tf32r(v.w));
            *(float4*)(Ab + (id >> 3) * LDS_ + (id & 7) * 4) = w;
        }
        if (NNB) {
#pragma unroll
            for (int c = 0; c < 2; c++) {
                float4 v = bR[c];
                int n = nn_n + 32 * c;
                Bb[(n + 0) * LDS_ + nn_k] = tf32r(v.x);
                Bb[(n + 1) * LDS_ + nn_k] = tf32r(v.y);
                Bb[(n + 2) * LDS_ + nn_k] = tf32r(v.z);
                Bb[(n + 3) * LDS_ + nn_k] = tf32r(v.w);
            }
        } else {
#pragma unroll
            for (int i = 0; i < 2; i++) {
                int id = tid + i * 256;
                float4 v = bR[i];
                float4 w = make_float4(tf32r(v.x), tf32r(v.y), tf32r(v.z), tf32r(v.w));
                *(float4*)(Bb + (id >> 3) * LDS_ + (id & 7) * 4) = w;
            }
        }
    };

    float acc[2][JT][4];
#pragma unroll
    for (int i = 0; i < 2; i++)
#pragma unroll
        for (int j = 0; j < JT; j++)
#pragma unroll
            for (int c = 0; c < 4; c++) acc[i][j][c] = 0.f;

    ldg(0);
    sts(0);
    __syncthreads();
    const int nk = K >> 5;
    for (int kt = 0; kt < nk; kt++) {
        int cur = kt & 1;
        if (kt + 1 < nk) ldg((kt + 1) * 32);
        uint32_t baseA = sA + (uint32_t)(cur * TBM * LDS_) * 4u;
        uint32_t baseB = sB + (uint32_t)(cur * BN * LDS_) * 4u;
#pragma unroll
        for (int kk = 0; kk < 32; kk += 8) {
            uint32_t a[2][4], b[NB16][4];
#pragma unroll
            for (int i = 0; i < 2; i++)
                ldsm4(a[i], baseA + (uint32_t)((wm + 16 * i + a_row) * LDS_ + kk + a_kad) * 4u);
#pragma unroll
            for (int j2 = 0; j2 < NB16; j2++)
                ldsm4(b[j2], baseB + (uint32_t)((wn + 16 * j2 + b_row) * LDS_ + kk + b_kad) * 4u);
#pragma unroll
            for (int i = 0; i < 2; i++)
#pragma unroll
                for (int j = 0; j < JT; j++)
                    mma_tf32(acc[i][j], a[i], b[j >> 1][(j & 1) * 2], b[j >> 1][(j & 1) * 2 + 1]);
        }
        if (kt + 1 < nk) {
            __syncthreads();
            sts(cur ^ 1);
            __syncthreads();
        }
    }

    const int r = lane >> 2, cp = (lane & 3) * 2;
#pragma unroll
    for (int i = 0; i < 2; i++) {
#pragma unroll
        for (int j = 0; j < JT; j++) {
            int row0 = bm + wm + 16 * i + r;
            int col  = bn + wn + 8 * j + cp;
            float2 bb2 = make_float2(0.f, 0.f);
            if (HAS_BIAS) bb2 = *(const float2*)(biasp + col);
            float2 v0 = make_float2(acc[i][j][0] + bb2.x, acc[i][j][1] + bb2.y);
            float2 v1 = make_float2(acc[i][j][2] + bb2.x, acc[i][j][3] + bb2.y);
            if (ACT) {
                v0.x = gelu_exact(v0.x); v0.y = gelu_exact(v0.y);
                v1.x = gelu_exact(v1.x); v1.y = gelu_exact(v1.y);
            }
            *(float2*)(Cz + (size_t)row0 * ldc + col) = v0;
            *(float2*)(Cz + (size_t)(row0 + 8) * ldc + col) = v1;
        }
    }
}

// ---------------------------------------------------------------- p2c gather staging
__global__ void p2c_gather_kernel() {
    __shared__ float sm[64][140];
    int z = blockIdx.z;
    int k0 = blockIdx.y * 64, q0 = blockIdx.x * 64;
    int tid = threadIdx.x;
    int w0 = p2ci(k0 + 63 - q0) & ~3;
    if (w0 > RSPAN - 136) w0 = RSPAN - 136;
    const float* src = g_p2c + (size_t)z * SEQ * RSPAN;
#pragma unroll
    for (int it = 0; it < 9; it++) {
        int idx = tid + it * 256;
        if (idx < 64 * 34) {
            int row = idx / 34, c = idx - row * 34;
            *(float4*)&sm[row][c * 4] =
                *(const float4*)(src + (size_t)(k0 + row) * RSPAN + w0 + c * 4);
        }
    }
    __syncthreads();
    float* dst = g_p2cg + (size_t)z * SEQ * SEQ;
    int kl = tid & 63;
    int qb = tid >> 6;
#pragma unroll
    for (int it = 0; it < 16; it++) {
        int ql = qb + it * 4;
        int idx = p2ci((k0 + kl) - (q0 + ql));
        dst[(size_t)(q0 + ql) * SEQ + k0 + kl] = sm[kl][idx - w0];
    }
}

// ---------------------------------------------------------------- combine + scale + mask + XSoftmax
__global__ void softmax_kernel() {
    __shared__ float red[256];
    __shared__ float smc[RSPAN];
    int zq = blockIdx.x;
    int z = zq >> 9, q = zq & 511;
    int bb = z / NHEAD;
    int tid = threadIdx.x;
    const float SCALE = sqrtf(192.0f);
    float mq = g_maskf[bb * SEQ + q];
    size_t rowS = ((size_t)z * SEQ + q) * SEQ;
    const float* c2pr = g_c2p + ((size_t)z * SEQ + q) * RSPAN;
    smc[tid] = c2pr[tid];
    smc[tid + 256] = c2pr[tid + 256];
    __syncthreads();

    int k0 = tid, k1 = tid + 256;
    float s0 = g_scores[rowS + k0] + smc[c2pi(q - k0)] + g_p2cg[rowS + k0];
    float s1 = g_scores[rowS + k1] + smc[c2pi(q - k1)] + g_p2cg[rowS + k1];
    s0 /= SCALE; s1 /= SCALE;
    bool m0 = (mq * g_maskf[bb * SEQ + k0]) > 0.f;
    bool m1 = (mq * g_maskf[bb * SEQ + k1]) > 0.f;
    float v0 = m0 ? s0 : -FLT_MAX;
    float v1 = m1 ? s1 : -FLT_MAX;

    red[tid] = fmaxf(v0, v1); __syncthreads();
    for (int s = 128; s; s >>= 1) { if (tid < s) red[tid] = fmaxf(red[tid], red[tid + s]); __syncthreads(); }
    float mx = red[0]; __syncthreads();

    float p0 = m0 ? expf(v0 - mx) : 0.f;
    float p1 = m1 ? expf(v1 - mx) : 0.f;
    red[tid] = p0 + p1; __syncthreads();
    for (int s = 128; s; s >>= 1) { if (tid < s) red[tid] += red[tid + s]; __syncthreads(); }
    float sum = red[0];
    float inv = (sum > 0.f) ? (1.0f / sum) : 0.f;
    g_scores[rowS + k0] = p0 * inv;
    g_scores[rowS + k1] = p1 * inv;
}

// ---------------------------------------------------------------- decoder + per-token NLL
__global__ void decoder_kernel(const float* __restrict__ tin, const float* __restrict__ Wd,
                               const float* __restrict__ bd, const int* __restrict__ labels,
                               float* __restrict__ out, int out_size) {
    __shared__ float sm[HID];
    __shared__ float red[256];
    __shared__ float lg[NCLS];
    int t = blockIdx.x, tid = threadIdx.x;
    for (int i = tid; i < HID; i += 256) sm[i] = tin[(size_t)t * HID + i];
    __syncthreads();
    for (int c = 0; c < NCLS; c++) {
        float p = 0.f;
        for (int k = tid; k < HID; k += 256) p += sm[k] * Wd[(size_t)k * NCLS + c];
        red[tid] = p; __syncthreads();
        for (int s = 128; s; s >>= 1) { if (tid < s) red[tid] += red[tid + s]; __syncthreads(); }
        if (tid == 0) lg[c] = red[0] + bd[c];
        __syncthreads();
    }
    if (out_size >= TOK * NCLS && tid < NCLS) out[(size_t)t * NCLS + tid] = lg[tid];
    if (tid == 0) {
        float mx = -FLT_MAX;
        for (int c = 0; c < NCLS; c++) mx = fmaxf(mx, lg[c]);
        float se = 0.f;
        for (int c = 0; c < NCLS; c++) se += expf(lg[c] - mx);
        float lse = mx + logf(se);
        g_nll[t] = (lse - lg[labels[t]]) * g_maskf[t];
    }
}

// ---------------------------------------------------------------- final deterministic loss reduce
__global__ void loss_kernel(float* __restrict__ out, int out_size) {
    __shared__ float rn[256], rd[256];
    int tid = threadIdx.x;
    float a = 0.f, d = 0.f;
    for (int t = tid; t < TOK; t += 256) { a += g_nll[t]; d += g_maskf[t]; }
    rn[tid] = a; rd[tid] = d; __syncthreads();
    for (int s = 128; s; s >>= 1) {
        if (tid < s) { rn[tid] += rn[tid + s]; rd[tid] += rd[tid + s]; }
        __syncthreads();
    }
    if (tid == 0) {
        float loss = rn[0] / fmaxf(rd[0], 1.0f);
        if (out_size > TOK * NCLS) out[TOK * NCLS] = loss;
        else if (out_size == 1)    out[0] = loss;
    }
}

// ---------------------------------------------------------------- launch
extern "C" void kernel_launch(void* const* d_in, const int* in_sizes, int n_in,
                              void* d_out, int out_size) {
    const float* word_emb = (const float*)d_in[0];
    const float* emb_ln_s = (const float*)d_in[1];
    const float* emb_ln_b = (const float*)d_in[2];
    const float* rel_emb  = (const float*)d_in[3];
    const float* rel_ln_s = (const float*)d_in[4];
    const float* rel_ln_b = (const float*)d_in[5];
    const float* Wq = (const float*)d_in[6];   const float* bq = (const float*)d_in[7];
    const float* Wk = (const float*)d_in[8];   const float* bk = (const float*)d_in[9];
    const float* Wv = (const float*)d_in[10];  const float* bv = (const float*)d_in[11];
    const float* Wo = (const float*)d_in[12];  const float* bo = (const float*)d_in[13];
    const float* ln1_s = (const float*)d_in[14]; const float* ln1_b = (const float*)d_in[15];
    const float* W1 = (const float*)d_in[16];  const float* b1 = (const float*)d_in[17];
    const float* W2 = (const float*)d_in[18];  const float* b2 = (const float*)d_in[19];
    const float* ln2_s = (const float*)d_in[20]; const float* ln2_b = (const float*)d_in[21];
    const float* Wt = (const float*)d_in[22];  const float* bt = (const float*)d_in[23];
    const float* tln_s = (const float*)d_in[24]; const float* tln_b = (const float*)d_in[25];
    const float* Wd = (const float*)d_in[26];  const float* bd = (const float*)d_in[27];
    const int* ids    = (const int*)d_in[28];
    const int* att    = (const int*)d_in[29];
    const int* labels = (const int*)d_in[30];
    float* out = (float*)d_out;
    (void)in_sizes; (void)n_in;

    cudaFuncSetAttribute(gemm_tc<4,1,1,0>, cudaFuncAttributeMaxDynamicSharedMemorySize, SMEM4);
    cudaFuncSetAttribute(gemm_tc<4,0,0,0>, cudaFuncAttributeMaxDynamicSharedMemorySize, SMEM4);
    cudaFuncSetAttribute(gemm_tc<4,1,1,1>, cudaFuncAttributeMaxDynamicSharedMemorySize, SMEM4);
    cudaFuncSetAttribute(gemm_tc<2,1,0,0>, cudaFuncAttributeMaxDynamicSharedMemorySize, SMEM2);
    cudaFuncSetAttribute(gemm_tc<2,1,1,0>, cudaFuncAttributeMaxDynamicSharedMemorySize, SMEM2);

    float *x, *qbuf, *ctx, *tmp, *relln, *qkv, *pos, *scores, *c2p, *p2c, *ff;
    cudaGetSymbolAddress((void**)&x, g_x);       cudaGetSymbolAddress((void**)&qbuf, g_q);
    cudaGetSymbolAddress((void**)&ctx, g_ctx);   cudaGetSymbolAddress((void**)&tmp, g_tmp);
    cudaGetSymbolAddress((void**)&relln, g_relln);
    cudaGetSymbolAddress((void**)&qkv, g_qkv);   cudaGetSymbolAddress((void**)&pos, g_pos);
    cudaGetSymbolAddress((void**)&scores, g_scores);
    cudaGetSymbolAddress((void**)&c2p, g_c2p);   cudaGetSymbolAddress((void**)&p2c, g_p2c);
    cudaGetSymbolAddress((void**)&ff, g_ff);

    embed_kernel<<<TOK, 256>>>(word_emb, emb_ln_s, emb_ln_b, ids, att);
    ln_kernel<<<RSPAN, 256>>>(rel_emb, rel_ln_s, rel_ln_b, relln);

    const long SH3 = (long)SEQ * 3 * HID;
    const long SS  = (long)SEQ * SEQ;
    const long SR  = (long)SEQ * RSPAN;
    const size_t HH = (size_t)HID * HID;

    auto mk = [](const float* A, const float* B, const float* bias, float* C,
                 long aB, long aH, long bB, long bH, long cB, long cH,
                 int lda, int ldb, int ldc) {
        GSet s; s.A = A; s.B = B; s.bias = bias; s.C = C;
        s.aB = aB; s.aH = aH; s.bB = bB; s.bH = bH; s.cB = cB; s.cH = cH;
        s.lda = lda; s.ldb = ldb; s.ldc = ldc; return s;
    };

    for (int l = 0; l < NLAYER; l++) {
        const float* wq = Wq + l * HH;  const float* bql = bq + (size_t)l * HID;
        const float* wk = Wk + l * HH;  const float* bkl = bk + (size_t)l * HID;
        const float* wv = Wv + l * HH;  const float* bvl = bv + (size_t)l * HID;
        const float* wo = Wo + l * HH;  const float* bol = bo + (size_t)l * HID;
        const float* w1 = W1 + (size_t)l * HID * FFD;  const float* b1l = b1 + (size_t)l * FFD;
        const float* w2 = W2 + (size_t)l * FFD * HID;  const float* b2l = b2 + (size_t)l * HID;

        // QKV: 3 sets in one launch (NN, weights direct), interleaved out [t][3*HID]
        {
            GSet sq = mk(x, wq, bql, qkv,         0,0,0,0,0,0, HID, HID, 3*HID);
            GSet sk = mk(x, wk, bkl, qkv + HID,   0,0,0,0,0,0, HID, HID, 3*HID);
            GSet sv = mk(x, wv, bvl, qkv + 2*HID, 0,0,0,0,0,0, HID, HID, 3*HID);
            gemm_tc<4,1,1,0><<<dim3(HID/BN, TOK/128, 3), 256, SMEM4>>>(sq, sk, sv, 1, HID);
        }
        // pos: posq|posk in one launch
        {
            GSet sq = mk(relln, wq, bql, pos,       0,0,0,0,0,0, HID, HID, 2*HID);
            GSet sk = mk(relln, wk, bkl, pos + HID, 0,0,0,0,0,0, HID, HID, 2*HID);
            gemm_tc<4,1,1,0><<<dim3(HID/BN, RSPAN/128, 2), 256, SMEM4>>>(sq, sk, sq, 1, HID);
        }
        // attention NT triple: scores / c2p / p2c in one launch (all M=512,N=512,K=64)
        {
            GSet ss = mk(qkv, qkv + HID, nullptr, scores,
                         SH3, HDIM, SH3, HDIM, (long)NHEAD*SS, SS, 3*HID, 3*HID, SEQ);
            GSet sc = mk(qkv, pos + HID, nullptr, c2p,
                         SH3, HDIM, 0, HDIM, (long)NHEAD*SR, SR, 3*HID, 2*HID, RSPAN);
            GSet sp = mk(qkv + HID, pos, nullptr, p2c,
                         SH3, HDIM, 0, HDIM, (long)NHEAD*SR, SR, 3*HID, 2*HID, RSPAN);
            gemm_tc<4,0,0,0><<<dim3(SEQ/BN, SEQ/128, 96), 256, SMEM4>>>(ss, sc, sp, ZBATCH, HDIM);
        }

        p2c_gather_kernel<<<dim3(SEQ/64, SEQ/64, ZBATCH), 256>>>();
        softmax_kernel<<<ZBATCH * SEQ, 256>>>();

        // ctx = probs @ V  (NN, V in-place, BM=64 => 256 blocks)
        {
            GSet sc = mk(scores, qkv + 2*HID, nullptr, ctx,
                         (long)NHEAD*SS, SS, SH3, HDIM, (long)SEQ*HID, HDIM, SEQ, 3*HID, HID);
            gemm_tc<2,1,0,0><<<dim3(HDIM/BN, SEQ/64, ZBATCH), 256, SMEM2>>>(sc, sc, sc, ZBATCH, SEQ);
        }
        // o-proj (BM=64 => 256 blocks)
        {
            GSet so = mk(ctx, wo, bol, tmp, 0,0,0,0,0,0, HID, HID, HID);
            gemm_tc<2,1,1,0><<<dim3(HID/BN, TOK/64, 1), 256, SMEM2>>>(so, so, so, 1, HID);
        }
        add_ln_kernel<<<TOK, 256>>>(x, tmp, ln1_s + (size_t)l*HID, ln1_b + (size_t)l*HID, x);

        // FFN
        {
            GSet s1 = mk(x, w1, b1l, ff, 0,0,0,0,0,0, HID, FFD, FFD);
            gemm_tc<4,1,1,1><<<dim3(FFD/BN, TOK/128, 1), 256, SMEM4>>>(s1, s1, s1, 1, HID);
        }
        {
            GSet s2 = mk(ff, w2, b2l, tmp, 0,0,0,0,0,0, FFD, HID, HID);
            gemm_tc<2,1,1,0><<<dim3(HID/BN, TOK/64, 1), 256, SMEM2>>>(s2, s2, s2, 1, FFD);
        }
        add_ln_kernel<<<TOK, 256>>>(x, tmp, ln2_s + (size_t)l*HID, ln2_b + (size_t)l*HID, x);
    }

    // transform head: LN(gelu(x @ Wt + bt))
    {
        GSet st = mk(x, Wt, bt, tmp, 0,0,0,0,0,0, HID, HID, HID);
        gemm_tc<4,1,1,1><<<dim3(HID/BN, TOK/128, 1), 256, SMEM4>>>(st, st, st, 1, HID);
    }
    ln_kernel<<<TOK, 256>>>(tmp, tln_s, tln_b, qbuf);

    decoder_kernel<<<TOK, 256>>>(qbuf, Wd, bd, labels, out, out_size);
    loss_kernel<<<1, 256>>>(out, out_size);
}